// round 15
// baseline (speedup 1.0000x reference)
#include <cuda_runtime.h>
#include <cuda_fp16.h>
#include <cstdint>

namespace {

constexpr int Bb = 64, Cc = 3, Hh = 384, Ww = 384, Pp = 16, Ee = 768;
constexpr int NP = (Hh / Pp) * (Ww / Pp);   // 576
constexpr int Mm = Bb * NP;                 // 36864
constexpr int Kk = Cc * Pp * Pp;            // 768

constexpr int BM = 128, BN = 128, BK = 32;  // CTA tile
constexpr int THREADS = 256;                // 8 warps: 2(M) x 4(N), 64x32 warp tiles
constexpr int SA = 40;                      // smem row stride fp16 (80B) - LDSM conflict-free
constexpr int NITER = Kk / BK;              // 24
constexpr int NSTAGE = 3;

constexpr int TILE_B  = BM * SA * 2;        // 10240 B per tile
constexpr int STAGE_B = 2 * TILE_B;         // A, B
constexpr int SMEM_B  = NSTAGE * STAGE_B;   // 61440 (2 CTAs/SM -> 120KB)

// fp16 operands, rebuilt every call.
__device__ __half g_wh[Ee * Kk];
__device__ __half g_ah[(size_t)Mm * Kk];

__device__ __forceinline__ uint32_t smem_u32(const void* p) {
    uint32_t a;
    asm("{ .reg .u64 t; cvta.to.shared.u64 t, %1; cvt.u32.u64 %0, t; }" : "=r"(a) : "l"(p));
    return a;
}
__device__ __forceinline__ void ldsm_x4(uint32_t addr, uint32_t& r0, uint32_t& r1,
                                        uint32_t& r2, uint32_t& r3) {
    asm volatile("ldmatrix.sync.aligned.m8n8.x4.shared.b16 {%0,%1,%2,%3}, [%4];"
                 : "=r"(r0), "=r"(r1), "=r"(r2), "=r"(r3) : "r"(addr));
}
__device__ __forceinline__ void mma_f16(float* d, const uint32_t* a, const uint32_t* b) {
    asm volatile(
        "mma.sync.aligned.m16n8k16.row.col.f32.f16.f16.f32 "
        "{%0,%1,%2,%3}, {%4,%5,%6,%7}, {%8,%9}, {%0,%1,%2,%3};"
        : "+f"(d[0]), "+f"(d[1]), "+f"(d[2]), "+f"(d[3])
        : "r"(a[0]), "r"(a[1]), "r"(a[2]), "r"(a[3]), "r"(b[0]), "r"(b[1]));
}
__device__ __forceinline__ void cp16(uint32_t dst, const void* src) {
    asm volatile("cp.async.cg.shared.global [%0], [%1], 16;" :: "r"(dst), "l"(src));
}
__device__ __forceinline__ void cp_commit() {
    asm volatile("cp.async.commit_group;" ::: "memory");
}
__device__ __forceinline__ void cp_wait1() {
    asm volatile("cp.async.wait_group 1;" ::: "memory");
}
__device__ __forceinline__ void cp_wait0() {
    asm volatile("cp.async.wait_group 0;" ::: "memory");
}

// Fused prep: blocks [0, WBLK) convert w -> fp16; the rest gather patches,
// convert to fp16 K-major [M,768], and write fp32 patch_positions.
constexpr int WBLK = Ee * Kk / (256 * 4);       // 576
constexpr int XBLK = Mm * 96 / 256;             // 13824

__global__ __launch_bounds__(256)
void prep_all(const float* __restrict__ w,
              const float* __restrict__ x,
              const int* __restrict__ ys, const int* __restrict__ xs,
              float* __restrict__ pos) {
    if (blockIdx.x < WBLK) {
        int i = (blockIdx.x * 256 + threadIdx.x) * 4;
        float4 v = *(const float4*)(w + i);
        __half2 a = __floats2half2_rn(v.x, v.y);
        __half2 b = __floats2half2_rn(v.z, v.w);
        *(uint2*)&g_wh[i] = make_uint2(*(uint32_t*)&a, *(uint32_t*)&b);
        return;
    }
    int t = (blockIdx.x - WBLK) * 256 + threadIdx.x;   // t < Mm * 96
    int m = t / 96, g = t - m * 96;
    int y0 = ys[m], x0 = xs[m];
    if (g == 0) {
        pos[2 * m + 0] = (float)y0;
        pos[2 * m + 1] = (float)x0;
    }
    int k0 = g * 8;
    int c = k0 >> 8, r = (k0 >> 4) & 15, q = k0 & 15;
    int bimg = m / NP;
    const float* src = x + ((size_t)(bimg * Cc + c) * Hh + y0 + r) * Ww + x0 + q;
    float v[8];
    #pragma unroll
    for (int j = 0; j < 8; ++j) v[j] = __ldg(src + j);
    uint32_t h[4];
    #pragma unroll
    for (int j = 0; j < 4; ++j) {
        __half2 p = __floats2half2_rn(v[2 * j], v[2 * j + 1]);
        h[j] = *(uint32_t*)&p;
    }
    *(uint4*)&g_ah[(size_t)m * Kk + k0] = make_uint4(h[0], h[1], h[2], h[3]);
}

// Single-product fp16 HMMA GEMM, 64x32 warp tiles (8 warps), 2 CTAs/SM,
// 3-stage cp.async pipeline. Bigger warp tiles cut LDSM traffic per HMMA
// by 25% (the profiled bottleneck: L1 61.9% > tensor 46.8%).
__global__ __launch_bounds__(THREADS, 2)
void patch_embed_hmma(const float* __restrict__ bias, float* __restrict__ out)
{
    extern __shared__ char smem[];
    const uint32_t sbase = smem_u32(smem);

    const int tid = threadIdx.x;
    const int warpid = tid >> 5, lane = tid & 31;
    const int wm = warpid & 1, wn = warpid >> 1;   // 2(M) x 4(N) warp grid
    const int m0 = blockIdx.y * BM, n0 = blockIdx.x * BN;

    // cp.async mapping: 256 threads = 128 rows x 2 halves; 2 cp16/half/tile.
    const int row = tid >> 1, half = tid & 1;
    const __half* asrc = g_ah + (size_t)(m0 + row) * Kk + half * 16;
    const __half* bsrc = g_wh + (size_t)(n0 + row) * Kk + half * 16;
    const uint32_t dst_off = (uint32_t)(row * (SA * 2) + half * 32);

    float acc[4][4][4];
    #pragma unroll
    for (int i = 0; i < 4; ++i)
        #pragma unroll
        for (int j = 0; j < 4; ++j)
            #pragma unroll
            for (int v = 0; v < 4; ++v) acc[i][j][v] = 0.f;

    // ldmatrix lane addressing (elements)
    const int g = lane >> 3, gi = lane & 7;
    const int aRow = wm * 64 + (g & 1) * 8 + gi;   // + mt*16, mt in 0..3
    const int aCol = (g >> 1) * 8;                 // + ks*16
    const int bRow = wn * 32 + (g >> 1) * 8 + gi;  // + np*16, np in 0..1
    const int bCol = (g & 1) * 8;                  // + ks*16

    // preload stages 0 and 1 as two separate groups
    #pragma unroll
    for (int s = 0; s < 2; ++s) {
        uint32_t d = sbase + s * STAGE_B + dst_off;
        cp16(d + 0 * TILE_B +  0, asrc + s * BK);
        cp16(d + 0 * TILE_B + 16, asrc + s * BK + 8);
        cp16(d + 1 * TILE_B +  0, bsrc + s * BK);
        cp16(d + 1 * TILE_B + 16, bsrc + s * BK + 8);
        cp_commit();
    }

    int stg_idx = 0;
    #pragma unroll 1
    for (int kt = 0; kt < NITER; ++kt) {
        cp_wait1();          // stage kt arrived (one younger group stays pending)
        __syncthreads();     // publish stage kt; fence cp-issue vs prev mma

        if (kt + 2 < NITER) {
            int s2 = stg_idx + 2; if (s2 >= NSTAGE) s2 -= NSTAGE;
            uint32_t d = sbase + s2 * STAGE_B + dst_off;
            int ko = (kt + 2) * BK;
            cp16(d + 0 * TILE_B +  0, asrc + ko);
            cp16(d + 0 * TILE_B + 16, asrc + ko + 8);
            cp16(d + 1 * TILE_B +  0, bsrc + ko);
            cp16(d + 1 * TILE_B + 16, bsrc + ko + 8);
        }
        cp_commit();         // always commit (keeps wait_group<1> arithmetic valid)

        const uint32_t stg = sbase + (uint32_t)(stg_idx * STAGE_B);
        #pragma unroll
        for (int ks = 0; ks < 2; ++ks) {
            const int kk = ks * 16;
            uint32_t aH[4][4], bH[4][2];
            #pragma unroll
            for (int mt = 0; mt < 4; ++mt) {
                uint32_t off = (uint32_t)(((aRow + mt * 16) * SA + aCol + kk) * 2);
                ldsm_x4(stg + 0 * TILE_B + off, aH[mt][0], aH[mt][1], aH[mt][2], aH[mt][3]);
            }
            #pragma unroll
            for (int np = 0; np < 2; ++np) {
                uint32_t off = (uint32_t)(((bRow + np * 16) * SA + bCol + kk) * 2);
                uint32_t r0, r1, r2, r3;
                ldsm_x4(stg + 1 * TILE_B + off, r0, r1, r2, r3);
                bH[np*2][0] = r0; bH[np*2][1] = r1; bH[np*2+1][0] = r2; bH[np*2+1][1] = r3;
            }
            #pragma unroll
            for (int mt = 0; mt < 4; ++mt)
                #pragma unroll
                for (int nt = 0; nt < 4; ++nt)
                    mma_f16(acc[mt][nt], aH[mt], bH[nt]);
        }

        if (++stg_idx == NSTAGE) stg_idx = 0;
    }
    cp_wait0();   // drain trailing empty groups

    // epilogue: fragments -> gmem, fused bias
    const int er = lane >> 2, ec = (lane & 3) * 2;
    float bv0[4], bv1[4];
    #pragma unroll
    for (int nt = 0; nt < 4; ++nt) {
        const int n = n0 + wn * 32 + nt * 8 + ec;
        bv0[nt] = __ldg(bias + n);
        bv1[nt] = __ldg(bias + n + 1);
    }
    #pragma unroll
    for (int mt = 0; mt < 4; ++mt) {
        #pragma unroll
        for (int nt = 0; nt < 4; ++nt) {
            const int n = n0 + wn * 32 + nt * 8 + ec;
            const int mrow = m0 + wm * 64 + mt * 16 + er;
            float2 v;
            v.x = acc[mt][nt][0] + bv0[nt]; v.y = acc[mt][nt][1] + bv1[nt];
            *(float2*)(out + (size_t)mrow * Ee + n) = v;
            v.x = acc[mt][nt][2] + bv0[nt]; v.y = acc[mt][nt][3] + bv1[nt];
            *(float2*)(out + (size_t)(mrow + 8) * Ee + n) = v;
        }
    }
}

} // namespace

extern "C" void kernel_launch(void* const* d_in, const int* in_sizes, int n_in,
                              void* d_out, int out_size) {
    const float* x    = (const float*)d_in[0];
    const int*   ys   = (const int*)d_in[1];
    const int*   xs   = (const int*)d_in[2];
    const float* w    = (const float*)d_in[3];
    const float* bias = (const float*)d_in[4];
    float* out = (float*)d_out;

    static int smem_set = 0;
    if (!smem_set) {
        cudaFuncSetAttribute(patch_embed_hmma,
                             cudaFuncAttributeMaxDynamicSharedMemorySize, SMEM_B);
        smem_set = 1;
    }

    float* pos = out + (size_t)Mm * Ee;
    prep_all<<<WBLK + XBLK, 256>>>(w, x, ys, xs, pos);

    dim3 grid(Ee / BN, Mm / BM);   // 6 x 288 = 1728 CTAs
    patch_embed_hmma<<<grid, THREADS, SMEM_B>>>(bias, out);
}

// round 16
// speedup vs baseline: 1.0994x; 1.0994x over previous
#include <cuda_runtime.h>
#include <cuda_fp16.h>
#include <cstdint>

namespace {

constexpr int Bb = 64, Cc = 3, Hh = 384, Ww = 384, Pp = 16, Ee = 768;
constexpr int NP = (Hh / Pp) * (Ww / Pp);   // 576
constexpr int Mm = Bb * NP;                 // 36864
constexpr int Kk = Cc * Pp * Pp;            // 768

constexpr int BM = 128, BN = 128, BK = 32;  // CTA tile
constexpr int THREADS = 512;                // 16 warps: 4(M) x 4(N), 32x32 tiles
constexpr int SA = 40;                      // smem row stride fp16 (80B) - LDSM conflict-free
constexpr int NITER = Kk / BK;              // 24
constexpr int NSTAGE = 4;                   // cp.async pipeline depth

constexpr int TILE_B  = BM * SA * 2;        // 10240 B per tile
constexpr int STAGE_B = 2 * TILE_B;         // A, B
constexpr int SMEM_B  = NSTAGE * STAGE_B;   // 81920 (2 CTAs/SM -> 160KB)

// fp16 operands, rebuilt every call.
__device__ __half g_wh[Ee * Kk];
__device__ __half g_ah[(size_t)Mm * Kk];

__device__ __forceinline__ uint32_t smem_u32(const void* p) {
    uint32_t a;
    asm("{ .reg .u64 t; cvta.to.shared.u64 t, %1; cvt.u32.u64 %0, t; }" : "=r"(a) : "l"(p));
    return a;
}
__device__ __forceinline__ void ldsm_x4(uint32_t addr, uint32_t& r0, uint32_t& r1,
                                        uint32_t& r2, uint32_t& r3) {
    asm volatile("ldmatrix.sync.aligned.m8n8.x4.shared.b16 {%0,%1,%2,%3}, [%4];"
                 : "=r"(r0), "=r"(r1), "=r"(r2), "=r"(r3) : "r"(addr));
}
__device__ __forceinline__ void mma_f16(float* d, const uint32_t* a, const uint32_t* b) {
    asm volatile(
        "mma.sync.aligned.m16n8k16.row.col.f32.f16.f16.f32 "
        "{%0,%1,%2,%3}, {%4,%5,%6,%7}, {%8,%9}, {%0,%1,%2,%3};"
        : "+f"(d[0]), "+f"(d[1]), "+f"(d[2]), "+f"(d[3])
        : "r"(a[0]), "r"(a[1]), "r"(a[2]), "r"(a[3]), "r"(b[0]), "r"(b[1]));
}
__device__ __forceinline__ void cp16(uint32_t dst, const void* src) {
    asm volatile("cp.async.cg.shared.global [%0], [%1], 16;" :: "r"(dst), "l"(src));
}
__device__ __forceinline__ void cp_commit() {
    asm volatile("cp.async.commit_group;" ::: "memory");
}
__device__ __forceinline__ void cp_wait2() {
    asm volatile("cp.async.wait_group 2;" ::: "memory");
}
__device__ __forceinline__ void cp_wait0() {
    asm volatile("cp.async.wait_group 0;" ::: "memory");
}

// Fused prep: blocks [0, WBLK) convert w -> fp16; the rest gather patches,
// convert to fp16 K-major [M,768], and write fp32 patch_positions.
constexpr int WBLK = Ee * Kk / (256 * 4);       // 576
constexpr int XBLK = Mm * 96 / 256;             // 13824

__global__ __launch_bounds__(256)
void prep_all(const float* __restrict__ w,
              const float* __restrict__ x,
              const int* __restrict__ ys, const int* __restrict__ xs,
              float* __restrict__ pos) {
    if (blockIdx.x < WBLK) {
        int i = (blockIdx.x * 256 + threadIdx.x) * 4;
        float4 v = *(const float4*)(w + i);
        __half2 a = __floats2half2_rn(v.x, v.y);
        __half2 b = __floats2half2_rn(v.z, v.w);
        *(uint2*)&g_wh[i] = make_uint2(*(uint32_t*)&a, *(uint32_t*)&b);
        return;
    }
    int t = (blockIdx.x - WBLK) * 256 + threadIdx.x;   // t < Mm * 96
    int m = t / 96, g = t - m * 96;
    int y0 = ys[m], x0 = xs[m];
    if (g == 0) {
        pos[2 * m + 0] = (float)y0;
        pos[2 * m + 1] = (float)x0;
    }
    int k0 = g * 8;
    int c = k0 >> 8, r = (k0 >> 4) & 15, q = k0 & 15;
    int bimg = m / NP;
    const float* src = x + ((size_t)(bimg * Cc + c) * Hh + y0 + r) * Ww + x0 + q;
    float v[8];
    #pragma unroll
    for (int j = 0; j < 8; ++j) v[j] = __ldg(src + j);
    uint32_t h[4];
    #pragma unroll
    for (int j = 0; j < 4; ++j) {
        __half2 p = __floats2half2_rn(v[2 * j], v[2 * j + 1]);
        h[j] = *(uint32_t*)&p;
    }
    *(uint4*)&g_ah[(size_t)m * Kk + k0] = make_uint4(h[0], h[1], h[2], h[3]);
}

// Single-product fp16 HMMA GEMM (fp32 accumulate), 32x32 warp tiles
// (regs=64 -> 2 CTAs/SM, 32 warps), 4-stage cp.async pipeline with
// wait_group 2: each cp group gets ~3 mma phases before its data is needed.
__global__ __launch_bounds__(THREADS, 2)
void patch_embed_hmma(const float* __restrict__ bias, float* __restrict__ out)
{
    extern __shared__ char smem[];
    const uint32_t sbase = smem_u32(smem);

    const int tid = threadIdx.x;
    const int warpid = tid >> 5, lane = tid & 31;
    const int wm = warpid & 3, wn = warpid >> 2;   // 4(M) x 4(N) warp grid
    const int m0 = blockIdx.y * BM, n0 = blockIdx.x * BN;

    // cp.async mapping: 512 threads = 128 rows x 4 chunks of 16B per tile.
    const int row = tid >> 2, c4 = tid & 3;
    const __half* asrc = g_ah + (size_t)(m0 + row) * Kk + c4 * 8;
    const __half* bsrc = g_wh + (size_t)(n0 + row) * Kk + c4 * 8;
    const uint32_t dst_off = (uint32_t)(row * (SA * 2) + c4 * 16);

    float acc[2][4][4];
    #pragma unroll
    for (int i = 0; i < 2; ++i)
        #pragma unroll
        for (int j = 0; j < 4; ++j)
            #pragma unroll
            for (int v = 0; v < 4; ++v) acc[i][j][v] = 0.f;

    // ldmatrix lane addressing (elements)
    const int g = lane >> 3, gi = lane & 7;
    const int aRow = wm * 32 + (g & 1) * 8 + gi;   // + mt*16
    const int aCol = (g >> 1) * 8;                 // + ks*16
    const int bRow = wn * 32 + (g >> 1) * 8 + gi;  // + np*16
    const int bCol = (g & 1) * 8;                  // + ks*16

    // preload stages 0..2 as three separate groups
    #pragma unroll
    for (int s = 0; s < 3; ++s) {
        uint32_t d = sbase + s * STAGE_B + dst_off;
        cp16(d + 0 * TILE_B, asrc + s * BK);
        cp16(d + 1 * TILE_B, bsrc + s * BK);
        cp_commit();
    }

    int stg_idx = 0;
    #pragma unroll 1
    for (int kt = 0; kt < NITER; ++kt) {
        cp_wait2();          // stage kt arrived (<=2 younger groups pending)
        __syncthreads();     // publish stage kt; fence cp-issue vs prev mma

        if (kt + 3 < NITER) {
            int s3 = stg_idx + 3; if (s3 >= NSTAGE) s3 -= NSTAGE;
            uint32_t d = sbase + s3 * STAGE_B + dst_off;
            int ko = (kt + 3) * BK;
            cp16(d + 0 * TILE_B, asrc + ko);
            cp16(d + 1 * TILE_B, bsrc + ko);
        }
        cp_commit();         // one group per iter keeps wait_group arithmetic valid

        const uint32_t stg = sbase + (uint32_t)(stg_idx * STAGE_B);
        #pragma unroll
        for (int ks = 0; ks < 2; ++ks) {
            const int kk = ks * 16;
            uint32_t aH[2][4], bH[4][2];
            #pragma unroll
            for (int mt = 0; mt < 2; ++mt) {
                uint32_t off = (uint32_t)(((aRow + mt * 16) * SA + aCol + kk) * 2);
                ldsm_x4(stg + 0 * TILE_B + off, aH[mt][0], aH[mt][1], aH[mt][2], aH[mt][3]);
            }
            #pragma unroll
            for (int np = 0; np < 2; ++np) {
                uint32_t off = (uint32_t)(((bRow + np * 16) * SA + bCol + kk) * 2);
                uint32_t r0, r1, r2, r3;
                ldsm_x4(stg + 1 * TILE_B + off, r0, r1, r2, r3);
                bH[np*2][0] = r0; bH[np*2][1] = r1; bH[np*2+1][0] = r2; bH[np*2+1][1] = r3;
            }
            #pragma unroll
            for (int mt = 0; mt < 2; ++mt)
                #pragma unroll
                for (int nt = 0; nt < 4; ++nt)
                    mma_f16(acc[mt][nt], aH[mt], bH[nt]);
        }

        if (++stg_idx == NSTAGE) stg_idx = 0;
    }
    cp_wait0();   // drain trailing empty groups

    // epilogue: fragments -> gmem, fused bias
    const int er = lane >> 2, ec = (lane & 3) * 2;
    #pragma unroll
    for (int mt = 0; mt < 2; ++mt) {
        #pragma unroll
        for (int nt = 0; nt < 4; ++nt) {
            const int n = n0 + wn * 32 + nt * 8 + ec;
            const float b0 = __ldg(bias + n), b1 = __ldg(bias + n + 1);
            const int mrow = m0 + wm * 32 + mt * 16 + er;
            float2 v;
            v.x = acc[mt][nt][0] + b0; v.y = acc[mt][nt][1] + b1;
            *(float2*)(out + (size_t)mrow * Ee + n) = v;
            v.x = acc[mt][nt][2] + b0; v.y = acc[mt][nt][3] + b1;
            *(float2*)(out + (size_t)(mrow + 8) * Ee + n) = v;
        }
    }
}

} // namespace

extern "C" void kernel_launch(void* const* d_in, const int* in_sizes, int n_in,
                              void* d_out, int out_size) {
    const float* x    = (const float*)d_in[0];
    const int*   ys   = (const int*)d_in[1];
    const int*   xs   = (const int*)d_in[2];
    const float* w    = (const float*)d_in[3];
    const float* bias = (const float*)d_in[4];
    float* out = (float*)d_out;

    static int smem_set = 0;
    if (!smem_set) {
        cudaFuncSetAttribute(patch_embed_hmma,
                             cudaFuncAttributeMaxDynamicSharedMemorySize, SMEM_B);
        smem_set = 1;
    }

    float* pos = out + (size_t)Mm * Ee;
    prep_all<<<WBLK + XBLK, 256>>>(w, x, ys, xs, pos);

    dim3 grid(Ee / BN, Mm / BM);   // 6 x 288 = 1728 CTAs
    patch_embed_hmma<<<grid, THREADS, SMEM_B>>>(bias, out);
}

// round 17
// speedup vs baseline: 1.1154x; 1.0145x over previous
#include <cuda_runtime.h>
#include <cuda_fp16.h>
#include <cstdint>

namespace {

constexpr int Bb = 64, Cc = 3, Hh = 384, Ww = 384, Pp = 16, Ee = 768;
constexpr int NP = (Hh / Pp) * (Ww / Pp);   // 576
constexpr int Mm = Bb * NP;                 // 36864
constexpr int Kk = Cc * Pp * Pp;            // 768

constexpr int BM = 128, BN = 128, BK = 64;  // CTA tile (BK=64: 12 iters)
constexpr int THREADS = 512;                // 16 warps: 4(M) x 4(N), 32x32 tiles
constexpr int SA = 72;                      // row stride fp16 (144B): banks 4i mod 32 -> conflict-free
constexpr int NITER = Kk / BK;              // 12
constexpr int NSTAGE = 3;

constexpr int TILE_B  = BM * SA * 2;        // 18432 B per tile
constexpr int STAGE_B = 2 * TILE_B;         // A, B
constexpr int SMEM_B  = NSTAGE * STAGE_B;   // 110592 (2 CTAs/SM -> 216KB)

// fp16 operands, rebuilt every call.
__device__ __half g_wh[Ee * Kk];
__device__ __half g_ah[(size_t)Mm * Kk];

__device__ __forceinline__ uint32_t smem_u32(const void* p) {
    uint32_t a;
    asm("{ .reg .u64 t; cvta.to.shared.u64 t, %1; cvt.u32.u64 %0, t; }" : "=r"(a) : "l"(p));
    return a;
}
__device__ __forceinline__ void ldsm_x4(uint32_t addr, uint32_t& r0, uint32_t& r1,
                                        uint32_t& r2, uint32_t& r3) {
    asm volatile("ldmatrix.sync.aligned.m8n8.x4.shared.b16 {%0,%1,%2,%3}, [%4];"
                 : "=r"(r0), "=r"(r1), "=r"(r2), "=r"(r3) : "r"(addr));
}
__device__ __forceinline__ void mma_f16(float* d, const uint32_t* a, const uint32_t* b) {
    asm volatile(
        "mma.sync.aligned.m16n8k16.row.col.f32.f16.f16.f32 "
        "{%0,%1,%2,%3}, {%4,%5,%6,%7}, {%8,%9}, {%0,%1,%2,%3};"
        : "+f"(d[0]), "+f"(d[1]), "+f"(d[2]), "+f"(d[3])
        : "r"(a[0]), "r"(a[1]), "r"(a[2]), "r"(a[3]), "r"(b[0]), "r"(b[1]));
}
__device__ __forceinline__ void cp16(uint32_t dst, const void* src) {
    asm volatile("cp.async.cg.shared.global [%0], [%1], 16;" :: "r"(dst), "l"(src));
}
__device__ __forceinline__ void cp_commit() {
    asm volatile("cp.async.commit_group;" ::: "memory");
}
__device__ __forceinline__ void cp_wait1() {
    asm volatile("cp.async.wait_group 1;" ::: "memory");
}
__device__ __forceinline__ void cp_wait0() {
    asm volatile("cp.async.wait_group 0;" ::: "memory");
}

// Fused prep: blocks [0, WBLK) convert w -> fp16; the rest gather patches,
// convert to fp16 K-major [M,768], and write fp32 patch_positions.
constexpr int WBLK = Ee * Kk / (256 * 4);       // 576
constexpr int XBLK = Mm * 96 / 256;             // 13824

__global__ __launch_bounds__(256)
void prep_all(const float* __restrict__ w,
              const float* __restrict__ x,
              const int* __restrict__ ys, const int* __restrict__ xs,
              float* __restrict__ pos) {
    if (blockIdx.x < WBLK) {
        int i = (blockIdx.x * 256 + threadIdx.x) * 4;
        float4 v = *(const float4*)(w + i);
        __half2 a = __floats2half2_rn(v.x, v.y);
        __half2 b = __floats2half2_rn(v.z, v.w);
        *(uint2*)&g_wh[i] = make_uint2(*(uint32_t*)&a, *(uint32_t*)&b);
        return;
    }
    int t = (blockIdx.x - WBLK) * 256 + threadIdx.x;   // t < Mm * 96
    int m = t / 96, g = t - m * 96;
    int y0 = ys[m], x0 = xs[m];
    if (g == 0) {
        pos[2 * m + 0] = (float)y0;
        pos[2 * m + 1] = (float)x0;
    }
    int k0 = g * 8;
    int c = k0 >> 8, r = (k0 >> 4) & 15, q = k0 & 15;
    int bimg = m / NP;
    const float* src = x + ((size_t)(bimg * Cc + c) * Hh + y0 + r) * Ww + x0 + q;
    float v[8];
    #pragma unroll
    for (int j = 0; j < 8; ++j) v[j] = __ldg(src + j);
    uint32_t h[4];
    #pragma unroll
    for (int j = 0; j < 4; ++j) {
        __half2 p = __floats2half2_rn(v[2 * j], v[2 * j + 1]);
        h[j] = *(uint32_t*)&p;
    }
    *(uint4*)&g_ah[(size_t)m * Kk + k0] = make_uint4(h[0], h[1], h[2], h[3]);
}

// Single-product fp16 HMMA GEMM, 32x32 warp tiles, 2 CTAs/SM, BK=64:
// 12 mainloop iterations instead of 24 to halve the measured ~870cyc/iter
// barrier/phase-start overhead (smem crossbar floor otherwise binding).
__global__ __launch_bounds__(THREADS, 2)
void patch_embed_hmma(const float* __restrict__ bias, float* __restrict__ out)
{
    extern __shared__ char smem[];
    const uint32_t sbase = smem_u32(smem);

    const int tid = threadIdx.x;
    const int warpid = tid >> 5, lane = tid & 31;
    const int wm = warpid & 3, wn = warpid >> 2;   // 4(M) x 4(N) warp grid
    const int m0 = blockIdx.y * BM, n0 = blockIdx.x * BN;

    // cp.async mapping: 512 threads = 128 rows x 4 chunks of 32B per tile.
    const int row = tid >> 2, c4 = tid & 3;
    const __half* asrc = g_ah + (size_t)(m0 + row) * Kk + c4 * 16;
    const __half* bsrc = g_wh + (size_t)(n0 + row) * Kk + c4 * 16;
    const uint32_t dst_off = (uint32_t)(row * (SA * 2) + c4 * 32);

    float acc[2][4][4];
    #pragma unroll
    for (int i = 0; i < 2; ++i)
        #pragma unroll
        for (int j = 0; j < 4; ++j)
            #pragma unroll
            for (int v = 0; v < 4; ++v) acc[i][j][v] = 0.f;

    // ldmatrix lane addressing (elements)
    const int g = lane >> 3, gi = lane & 7;
    const int aRow = wm * 32 + (g & 1) * 8 + gi;   // + mt*16
    const int aCol = (g >> 1) * 8;                 // + ks*16
    const int bRow = wn * 32 + (g >> 1) * 8 + gi;  // + np*16
    const int bCol = (g & 1) * 8;                  // + ks*16

    // preload stages 0 and 1 as two separate groups
    #pragma unroll
    for (int s = 0; s < 2; ++s) {
        uint32_t d = sbase + s * STAGE_B + dst_off;
        cp16(d + 0 * TILE_B +  0, asrc + s * BK);
        cp16(d + 0 * TILE_B + 16, asrc + s * BK + 8);
        cp16(d + 1 * TILE_B +  0, bsrc + s * BK);
        cp16(d + 1 * TILE_B + 16, bsrc + s * BK + 8);
        cp_commit();
    }

    int stg_idx = 0;
    #pragma unroll 1
    for (int kt = 0; kt < NITER; ++kt) {
        cp_wait1();          // stage kt arrived (one younger group stays pending)
        __syncthreads();     // publish stage kt; fence cp-issue vs prev mma

        if (kt + 2 < NITER) {
            int s2 = stg_idx + 2; if (s2 >= NSTAGE) s2 -= NSTAGE;
            uint32_t d = sbase + s2 * STAGE_B + dst_off;
            int ko = (kt + 2) * BK;
            cp16(d + 0 * TILE_B +  0, asrc + ko);
            cp16(d + 0 * TILE_B + 16, asrc + ko + 8);
            cp16(d + 1 * TILE_B +  0, bsrc + ko);
            cp16(d + 1 * TILE_B + 16, bsrc + ko + 8);
        }
        cp_commit();         // one group per iter keeps wait_group arithmetic valid

        const uint32_t stg = sbase + (uint32_t)(stg_idx * STAGE_B);
        #pragma unroll
        for (int ks = 0; ks < 4; ++ks) {
            const int kk = ks * 16;
            uint32_t aH[2][4], bH[4][2];
            #pragma unroll
            for (int mt = 0; mt < 2; ++mt) {
                uint32_t off = (uint32_t)(((aRow + mt * 16) * SA + aCol + kk) * 2);
                ldsm_x4(stg + 0 * TILE_B + off, aH[mt][0], aH[mt][1], aH[mt][2], aH[mt][3]);
            }
            #pragma unroll
            for (int np = 0; np < 2; ++np) {
                uint32_t off = (uint32_t)(((bRow + np * 16) * SA + bCol + kk) * 2);
                uint32_t r0, r1, r2, r3;
                ldsm_x4(stg + 1 * TILE_B + off, r0, r1, r2, r3);
                bH[np*2][0] = r0; bH[np*2][1] = r1; bH[np*2+1][0] = r2; bH[np*2+1][1] = r3;
            }
            #pragma unroll
            for (int mt = 0; mt < 2; ++mt)
                #pragma unroll
                for (int nt = 0; nt < 4; ++nt)
                    mma_f16(acc[mt][nt], aH[mt], bH[nt]);
        }

        if (++stg_idx == NSTAGE) stg_idx = 0;
    }
    cp_wait0();   // drain trailing empty groups

    // epilogue: fragments -> gmem, fused bias
    const int er = lane >> 2, ec = (lane & 3) * 2;
    #pragma unroll
    for (int mt = 0; mt < 2; ++mt) {
        #pragma unroll
        for (int nt = 0; nt < 4; ++nt) {
            const int n = n0 + wn * 32 + nt * 8 + ec;
            const float b0 = __ldg(bias + n), b1 = __ldg(bias + n + 1);
            const int mrow = m0 + wm * 32 + mt * 16 + er;
            float2 v;
            v.x = acc[mt][nt][0] + b0; v.y = acc[mt][nt][1] + b1;
            *(float2*)(out + (size_t)mrow * Ee + n) = v;
            v.x = acc[mt][nt][2] + b0; v.y = acc[mt][nt][3] + b1;
            *(float2*)(out + (size_t)(mrow + 8) * Ee + n) = v;
        }
    }
}

} // namespace

extern "C" void kernel_launch(void* const* d_in, const int* in_sizes, int n_in,
                              void* d_out, int out_size) {
    const float* x    = (const float*)d_in[0];
    const int*   ys   = (const int*)d_in[1];
    const int*   xs   = (const int*)d_in[2];
    const float* w    = (const float*)d_in[3];
    const float* bias = (const float*)d_in[4];
    float* out = (float*)d_out;

    static int smem_set = 0;
    if (!smem_set) {
        cudaFuncSetAttribute(patch_embed_hmma,
                             cudaFuncAttributeMaxDynamicSharedMemorySize, SMEM_B);
        smem_set = 1;
    }

    float* pos = out + (size_t)Mm * Ee;
    prep_all<<<WBLK + XBLK, 256>>>(w, x, ys, xs, pos);

    dim3 grid(Ee / BN, Mm / BM);   // 6 x 288 = 1728 CTAs
    patch_embed_hmma<<<grid, THREADS, SMEM_B>>>(bias, out);
}